// round 7
// baseline (speedup 1.0000x reference)
#include <cuda_runtime.h>
#include <cstdint>

#define HID 128
#define NN 50000
#define NE 800000
#define NG 64
#define NL 2

// ---------------- scratch (static device allocations) ----------------
__device__ __align__(16) float g_Xn[NN * HID];   // normed layer input (edge gather source)
__device__ __align__(16) float g_M[NN * HID];    // normed X + edge aggregation (gemm1 input)
__device__ __align__(16) float g_A[NN * HID];    // gemm1 output
__device__ __align__(16) float g_R[NN * HID];    // gemm2 raw output
__device__ double g_sum[HID];
__device__ double g_sumsq[HID];
__device__ __align__(16) float g_scale[HID];
__device__ __align__(16) float g_shift[HID];

__device__ __forceinline__ uint32_t f2tf32(float v) {
    uint32_t o;
    asm("cvt.rna.tf32.f32 %0, %1;" : "=r"(o) : "f"(v));
    return o;
}
__device__ __forceinline__ void split_tf32(float v, uint32_t& h, uint32_t& l) {
    h = f2tf32(v);
    l = f2tf32(v - __uint_as_float(h));
}

#define MMA_TF32(d, a, b) \
    asm volatile("mma.sync.aligned.m16n8k8.row.col.f32.tf32.tf32.f32 " \
        "{%0,%1,%2,%3}, {%4,%5,%6,%7}, {%8,%9}, {%0,%1,%2,%3};" \
        : "+f"((d)[0]), "+f"((d)[1]), "+f"((d)[2]), "+f"((d)[3]) \
        : "r"((a)[0]), "r"((a)[1]), "r"((a)[2]), "r"((a)[3]), \
          "r"((b)[0]), "r"((b)[1]))

// ---------------- embed: Xn = M = node_emb[x_idx] (layer0 norm = identity) ----------------
__global__ void embed_kernel(const int* __restrict__ xi, const float* __restrict__ nemb) {
    int i = blockIdx.x * blockDim.x + threadIdx.x;
    if (i >= NN * (HID / 4)) return;
    int n = i >> 5;
    int c = i & 31;
    float4 v = __ldg((const float4*)(nemb + xi[n] * HID) + c);
    ((float4*)g_Xn)[i] = v;
    ((float4*)g_M)[i] = v;
}

// ---------------- init (between layers): Xn = M = norm(R) ----------------
__global__ void init_kernel(const float* __restrict__ R) {
    int i = blockIdx.x * blockDim.x + threadIdx.x;
    if (i >= NN * (HID / 4)) return;
    int c = i & 31;
    float4 v = __ldg((const float4*)R + i);
    float4 sc = *(const float4*)(g_scale + c * 4);
    float4 sh = *(const float4*)(g_shift + c * 4);
    v.x = fmaf(v.x, sc.x, sh.x);
    v.y = fmaf(v.y, sc.y, sh.y);
    v.z = fmaf(v.z, sc.z, sh.z);
    v.w = fmaf(v.w, sc.w, sh.w);
    ((float4*)g_Xn)[i] = v;
    ((float4*)g_M)[i] = v;
}

// ---------------- edge: M[dst] += relu(Xn[src] + edge_emb[attr]) ----------------
__global__ void edge_kernel(const float* __restrict__ Xn, float* __restrict__ M,
                            const int* __restrict__ ei, const int* __restrict__ ea,
                            const float* __restrict__ eemb) {
    int warp = (blockIdx.x * blockDim.x + threadIdx.x) >> 5;
    int lane = threadIdx.x & 31;
    int base = warp * 8;
#pragma unroll
    for (int j = 0; j < 8; j++) {
        int e = base + j;
        if (e >= NE) break;
        int src  = __ldg(ei + e);
        int dst  = __ldg(ei + NE + e);
        int attr = __ldg(ea + e);
        float4 x4 = __ldg((const float4*)(Xn + src * HID) + lane);
        float4 e4 = __ldg((const float4*)(eemb + attr * HID) + lane);
        float4 m;
        m.x = fmaxf(x4.x + e4.x, 0.f);
        m.y = fmaxf(x4.y + e4.y, 0.f);
        m.z = fmaxf(x4.z + e4.z, 0.f);
        m.w = fmaxf(x4.w + e4.w, 0.f);
        float* p = M + dst * HID + lane * 4;
        asm volatile("red.global.add.v4.f32 [%0], {%1,%2,%3,%4};"
                     :: "l"(p), "f"(m.x), "f"(m.y), "f"(m.z), "f"(m.w) : "memory");
    }
}

// ---------------- 3xTF32 HMMA GEMM with cp.async pipeline ----------------
// C = relu(A @ W + bias); STATS accumulates BN column stats.
// Block 512 thr, CTA tile 256x128, warp grid 8Mx2N, warp tile 32x64.
// Smem: W fragment-major hi/lo (128KB), raw A double-buffered K=32 chunks
//       [256][36] (36KB x2), stats (1KB). ~201KB -> 1 CTA/SM.
#define MTILE 256
#define RS 36
#define RAW_WORDS (MTILE * RS)
#define WF_WORDS 16384
#define RAW_OFF (2 * WF_WORDS)
#define STAT_OFF (RAW_OFF + 2 * RAW_WORDS)
#define SMEM_GEMM ((STAT_OFF + 256) * 4)

template <bool STATS>
__global__ void __launch_bounds__(512, 1)
gemm_mma_kernel(const float* __restrict__ A, const float* __restrict__ W,
                const float* __restrict__ bias, float* __restrict__ C) {
    extern __shared__ char smem[];
    uint32_t* Wf = (uint32_t*)smem;                 // hi [0,16384), lo [16384,32768)
    float* raw = (float*)(Wf + RAW_OFF);
    float* ssum = (float*)(Wf + STAT_OFF);
    float* ssq = ssum + 128;

    uint32_t smem_base;
    asm("{ .reg .u64 t; cvta.to.shared.u64 t, %1; cvt.u32.u64 %0, t; }"
        : "=r"(smem_base) : "l"(smem));
    uint32_t rawAddr = smem_base + RAW_OFF * 4u;

    int tid = threadIdx.x, wid = tid >> 5, lane = tid & 31;
    int wm = wid & 7, wn = wid >> 3;
    int g = lane >> 2, tg = lane & 3;
    int rowBase = blockIdx.x * MTILE;

    if (STATS && tid < 256) ssum[tid] = 0.f;

    // issue a K=32 chunk of A via cp.async (2048 x 16B)
    auto issue_chunk = [&](int chunk, int buf) {
#pragma unroll
        for (int j = 0; j < 4; j++) {
            int i = tid + j * 512;
            int r = i >> 3, q = i & 7;
            int grow = rowBase + r;
            const float* src = A + (size_t)min(grow, NN - 1) * HID + chunk * 32 + q * 4;
            uint32_t dst = rawAddr + (uint32_t)(buf * RAW_WORDS + r * RS + q * 4) * 4u;
            int sz = (grow < NN) ? 16 : 0;
            asm volatile("cp.async.cg.shared.global [%0], [%1], 16, %2;"
                         :: "r"(dst), "l"(src), "r"(sz));
        }
        asm volatile("cp.async.commit_group;");
    };
    issue_chunk(0, 0);
    issue_chunk(1, 1);

    // stage W fragment-major, hi/lo split (overlaps with cp.async flight)
    for (int i = tid; i < 4096; i += 512) {
        int k = i >> 5, c4 = (i & 31) << 2;
        float4 v = __ldg((const float4*)(W + k * HID + c4));
        int kstep = k >> 3;
        int word = (k >> 2) & 1;
        int tgk = k & 3;
#pragma unroll
        for (int t = 0; t < 4; t++) {
            float x = (&v.x)[t];
            int n = c4 + t;
            int fw = ((n >> 6) * 8 + ((n >> 3) & 7)) * 16 + kstep;
            int la = (n & 7) * 4 + tgk;
            uint32_t h, l;
            split_tf32(x, h, l);
            Wf[fw * 64 + la * 2 + word] = h;
            Wf[WF_WORDS + fw * 64 + la * 2 + word] = l;
        }
    }

    float acc[2][8][4];
#pragma unroll
    for (int mt = 0; mt < 2; mt++)
#pragma unroll
        for (int nt = 0; nt < 8; nt++)
#pragma unroll
            for (int c = 0; c < 4; c++) acc[mt][nt][c] = 0.f;

#pragma unroll
    for (int chunk = 0; chunk < 4; chunk++) {
        if (chunk < 3) asm volatile("cp.async.wait_group 1;" ::: "memory");
        else           asm volatile("cp.async.wait_group 0;" ::: "memory");
        __syncthreads();
        const float* rb = raw + (chunk & 1) * RAW_WORDS;

#pragma unroll
        for (int ks = 0; ks < 4; ks++) {
            int k0 = ks * 8;
            uint32_t afH[2][4], afL[2][4];
#pragma unroll
            for (int mt = 0; mt < 2; mt++) {
                int r = wm * 32 + mt * 16 + g;
                float v0 = rb[r * RS + k0 + tg];
                float v1 = rb[(r + 8) * RS + k0 + tg];
                float v2 = rb[r * RS + k0 + tg + 4];
                float v3 = rb[(r + 8) * RS + k0 + tg + 4];
                split_tf32(v0, afH[mt][0], afL[mt][0]);
                split_tf32(v1, afH[mt][1], afL[mt][1]);
                split_tf32(v2, afH[mt][2], afL[mt][2]);
                split_tf32(v3, afH[mt][3], afL[mt][3]);
            }
            int kstep = chunk * 4 + ks;
#pragma unroll
            for (int hb = 0; hb < 2; hb++) {
                uint32_t bfH[4][2], bfL[4][2];
#pragma unroll
                for (int q = 0; q < 4; q++) {
                    int nt = hb * 4 + q;
                    int fw = (wn * 8 + nt) * 16 + kstep;
                    uint2 vh = *(const uint2*)(Wf + fw * 64 + lane * 2);
                    uint2 vl = *(const uint2*)(Wf + WF_WORDS + fw * 64 + lane * 2);
                    bfH[q][0] = vh.x; bfH[q][1] = vh.y;
                    bfL[q][0] = vl.x; bfL[q][1] = vl.y;
                }
#pragma unroll
                for (int mt = 0; mt < 2; mt++)
#pragma unroll
                    for (int q = 0; q < 4; q++) {
                        int nt = hb * 4 + q;
                        MMA_TF32(acc[mt][nt], afH[mt], bfL[q]);
                        MMA_TF32(acc[mt][nt], afL[mt], bfH[q]);
                        MMA_TF32(acc[mt][nt], afH[mt], bfH[q]);
                    }
            }
        }
        __syncthreads();
        if (chunk < 2) issue_chunk(chunk + 2, chunk & 1);
    }

    // epilogue: bias + relu, stores, optional column stats
#pragma unroll
    for (int nt = 0; nt < 8; nt++) {
        int col = wn * 64 + nt * 8 + tg * 2;
        float2 bv = __ldg((const float2*)(bias + col));
        float s0 = 0.f, s1 = 0.f, q0 = 0.f, q1 = 0.f;
#pragma unroll
        for (int mt = 0; mt < 2; mt++) {
            int r0 = rowBase + wm * 32 + mt * 16 + g;
            float2 oa, ob;
            oa.x = fmaxf(acc[mt][nt][0] + bv.x, 0.f);
            oa.y = fmaxf(acc[mt][nt][1] + bv.y, 0.f);
            ob.x = fmaxf(acc[mt][nt][2] + bv.x, 0.f);
            ob.y = fmaxf(acc[mt][nt][3] + bv.y, 0.f);
            if (r0 < NN) {
                *(float2*)(C + r0 * HID + col) = oa;
                if (STATS) { s0 += oa.x; q0 += oa.x * oa.x; s1 += oa.y; q1 += oa.y * oa.y; }
            }
            if (r0 + 8 < NN) {
                *(float2*)(C + (r0 + 8) * HID + col) = ob;
                if (STATS) { s0 += ob.x; q0 += ob.x * ob.x; s1 += ob.y; q1 += ob.y * ob.y; }
            }
        }
        if (STATS) {
#pragma unroll
            for (int m = 16; m >= 4; m >>= 1) {
                s0 += __shfl_xor_sync(0xffffffff, s0, m);
                s1 += __shfl_xor_sync(0xffffffff, s1, m);
                q0 += __shfl_xor_sync(0xffffffff, q0, m);
                q1 += __shfl_xor_sync(0xffffffff, q1, m);
            }
            if (lane < 4) {
                int c0 = wn * 64 + nt * 8 + lane * 2;
                atomicAdd(&ssum[c0], s0);
                atomicAdd(&ssum[c0 + 1], s1);
                atomicAdd(&ssq[c0], q0);
                atomicAdd(&ssq[c0 + 1], q1);
            }
        }
    }
    if (STATS) {
        __syncthreads();
        if (tid < 128) {
            atomicAdd(&g_sum[tid], (double)ssum[tid]);
            atomicAdd(&g_sumsq[tid], (double)ssq[tid]);
        }
    }
}

// ---------------- finalize: scale/shift from stats; reset accumulators ----------------
__global__ void finalize_kernel(const float* __restrict__ gw, const float* __restrict__ bw) {
    int c = threadIdx.x;
    double mu = g_sum[c] / (double)NN;
    double var = g_sumsq[c] / (double)NN - mu * mu;
    float sc = (float)((double)gw[c] * rsqrt(var + 1e-5));
    g_scale[c] = sc;
    g_shift[c] = bw[c] - (float)mu * sc;
    g_sum[c] = 0.0;
    g_sumsq[c] = 0.0;
}

// ---------------- pooling (applies final norm inline) ----------------
__global__ void zero_out_kernel(float* out) {
    int i = blockIdx.x * blockDim.x + threadIdx.x;
    if (i < NG * HID) out[i] = 0.f;
}

__global__ void pool_kernel(const float* __restrict__ R, const int* __restrict__ batch,
                            float* __restrict__ out) {
    int warp = (blockIdx.x * blockDim.x + threadIdx.x) >> 5;
    int lane = threadIdx.x & 31;
    if (warp >= NN) return;
    float4 sc = *(const float4*)(g_scale + lane * 4);
    float4 sh = *(const float4*)(g_shift + lane * 4);
    int g = __ldg(batch + warp);
    float4 v = __ldg((const float4*)(R + warp * HID) + lane);
    v.x = fmaf(v.x, sc.x, sh.x);
    v.y = fmaf(v.y, sc.y, sh.y);
    v.z = fmaf(v.z, sc.z, sh.z);
    v.w = fmaf(v.w, sc.w, sh.w);
    float* p = out + g * HID + lane * 4;
    asm volatile("red.global.add.v4.f32 [%0], {%1,%2,%3,%4};"
                 :: "l"(p), "f"(v.x), "f"(v.y), "f"(v.z), "f"(v.w) : "memory");
}

// ---------------- host ----------------
extern "C" void kernel_launch(void* const* d_in, const int* in_sizes, int n_in,
                              void* d_out, int out_size) {
    const int*   x_idx      = (const int*)d_in[0];
    const int*   edge_index = (const int*)d_in[1];
    const int*   edge_attr  = (const int*)d_in[2];
    const int*   batch      = (const int*)d_in[3];
    const float* node_emb   = (const float*)d_in[4];
    const float* edge_emb   = (const float*)d_in[5];
    const float* W1         = (const float*)d_in[6];
    const float* b1         = (const float*)d_in[7];
    const float* W2         = (const float*)d_in[8];
    const float* b2         = (const float*)d_in[9];
    const float* bn_g       = (const float*)d_in[10];
    const float* bn_b       = (const float*)d_in[11];
    float* out = (float*)d_out;

    cudaFuncSetAttribute(gemm_mma_kernel<false>,
                         cudaFuncAttributeMaxDynamicSharedMemorySize, SMEM_GEMM);
    cudaFuncSetAttribute(gemm_mma_kernel<true>,
                         cudaFuncAttributeMaxDynamicSharedMemorySize, SMEM_GEMM);

    float *Xn, *M, *Ap, *R;
    cudaGetSymbolAddress((void**)&Xn, g_Xn);
    cudaGetSymbolAddress((void**)&M, g_M);
    cudaGetSymbolAddress((void**)&Ap, g_A);
    cudaGetSymbolAddress((void**)&R, g_R);

    int nf4 = NN * (HID / 4);
    int cpBlocks = (nf4 + 255) / 256;
    int gemmBlocks = (NN + MTILE - 1) / MTILE;

    embed_kernel<<<cpBlocks, 256>>>(x_idx, node_emb);

    for (int l = 0; l < NL; l++) {
        if (l > 0) init_kernel<<<cpBlocks, 256>>>(R);
        edge_kernel<<<NE / 64, 256>>>(Xn, M, edge_index, edge_attr, edge_emb);
        gemm_mma_kernel<false><<<gemmBlocks, 512, SMEM_GEMM>>>(
            M, W1 + l * HID * HID, b1 + l * HID, Ap);
        gemm_mma_kernel<true><<<gemmBlocks, 512, SMEM_GEMM>>>(
            Ap, W2 + l * HID * HID, b2 + l * HID, R);
        finalize_kernel<<<1, 128>>>(bn_g + l * HID, bn_b + l * HID);
    }

    zero_out_kernel<<<(NG * HID + 255) / 256, 256>>>(out);
    pool_kernel<<<NN * 32 / 256, 256>>>(R, batch, out);
}

// round 8
// speedup vs baseline: 1.3018x; 1.3018x over previous
#include <cuda_runtime.h>
#include <cstdint>

#define HID 128
#define NN 50000
#define NE 800000
#define NG 64
#define NL 2

// ---------------- scratch (static device allocations) ----------------
__device__ __align__(16) float g_Xn[NN * HID];   // normed layer input (edge gather source)
__device__ __align__(16) float g_M[NN * HID];    // normed X + edge aggregation (gemm1 input)
__device__ __align__(16) float g_A[NN * HID];    // gemm1 output
__device__ __align__(16) float g_R[NN * HID];    // gemm2 raw output
__device__ __align__(16) uint32_t g_Wf[4 * 32768]; // fragment-major hi/lo weights
__device__ double g_sum[HID];
__device__ double g_sumsq[HID];
__device__ __align__(16) float g_scale[HID];
__device__ __align__(16) float g_shift[HID];

__device__ __forceinline__ uint32_t f2tf32(float v) {
    uint32_t o;
    asm("cvt.rna.tf32.f32 %0, %1;" : "=r"(o) : "f"(v));
    return o;
}
__device__ __forceinline__ void split_tf32(float v, uint32_t& h, uint32_t& l) {
    h = f2tf32(v);
    l = f2tf32(v - __uint_as_float(h));
}

#define MMA_TF32(d, a, b) \
    asm volatile("mma.sync.aligned.m16n8k8.row.col.f32.tf32.tf32.f32 " \
        "{%0,%1,%2,%3}, {%4,%5,%6,%7}, {%8,%9}, {%0,%1,%2,%3};" \
        : "+f"((d)[0]), "+f"((d)[1]), "+f"((d)[2]), "+f"((d)[3]) \
        : "r"((a)[0]), "r"((a)[1]), "r"((a)[2]), "r"((a)[3]), \
          "r"((b)[0]), "r"((b)[1]))

// ---------------- weight prep: fragment-major hi/lo layout ----------------
// For W[k][n] (row-major k x n): kstep=k>>3, nf=n>>3, lane=(n&7)*4+(k&3), word=(k>>2)&1.
// uint4 slot per (w, kstep, nf, lane): {b0_hi, b1_hi, b0_lo, b1_lo}.
__global__ void prep_w_kernel(const float* __restrict__ W1, const float* __restrict__ W2) {
    int i = blockIdx.x * blockDim.x + threadIdx.x;
    if (i >= 4 * HID * HID) return;
    int w = i >> 14;
    int k = (i >> 7) & 127;
    int n = i & 127;
    int l = w >> 1;
    const float* W = (w & 1) ? W2 : W1;
    float v = __ldg(W + l * HID * HID + k * HID + n);
    uint32_t h, lo;
    split_tf32(v, h, lo);
    int lane = (n & 7) * 4 + (k & 3);
    int word = (k >> 2) & 1;
    int base4 = ((w * 256 + (k >> 3) * 16 + (n >> 3)) * 32 + lane) * 4;
    g_Wf[base4 + word] = h;
    g_Wf[base4 + 2 + word] = lo;
}

// ---------------- embed: Xn = M = node_emb[x_idx] (layer0 norm = identity) ----------------
__global__ void embed_kernel(const int* __restrict__ xi, const float* __restrict__ nemb) {
    int i = blockIdx.x * blockDim.x + threadIdx.x;
    if (i >= NN * (HID / 4)) return;
    int n = i >> 5;
    int c = i & 31;
    float4 v = __ldg((const float4*)(nemb + xi[n] * HID) + c);
    ((float4*)g_Xn)[i] = v;
    ((float4*)g_M)[i] = v;
}

// ---------------- init (between layers): Xn = M = norm(R) ----------------
__global__ void init_kernel(const float* __restrict__ R) {
    int i = blockIdx.x * blockDim.x + threadIdx.x;
    if (i >= NN * (HID / 4)) return;
    int c = i & 31;
    float4 v = __ldg((const float4*)R + i);
    float4 sc = *(const float4*)(g_scale + c * 4);
    float4 sh = *(const float4*)(g_shift + c * 4);
    v.x = fmaf(v.x, sc.x, sh.x);
    v.y = fmaf(v.y, sc.y, sh.y);
    v.z = fmaf(v.z, sc.z, sh.z);
    v.w = fmaf(v.w, sc.w, sh.w);
    ((float4*)g_Xn)[i] = v;
    ((float4*)g_M)[i] = v;
}

// ---------------- edge: M[dst] += relu(Xn[src] + edge_emb[attr]) ----------------
__global__ void edge_kernel(const float* __restrict__ Xn, float* __restrict__ M,
                            const int* __restrict__ ei, const int* __restrict__ ea,
                            const float* __restrict__ eemb) {
    int warp = (blockIdx.x * blockDim.x + threadIdx.x) >> 5;
    int lane = threadIdx.x & 31;
    int base = warp * 8;
#pragma unroll
    for (int j = 0; j < 8; j++) {
        int e = base + j;
        if (e >= NE) break;
        int src  = __ldg(ei + e);
        int dst  = __ldg(ei + NE + e);
        int attr = __ldg(ea + e);
        float4 x4 = __ldg((const float4*)(Xn + src * HID) + lane);
        float4 e4 = __ldg((const float4*)(eemb + attr * HID) + lane);
        float4 m;
        m.x = fmaxf(x4.x + e4.x, 0.f);
        m.y = fmaxf(x4.y + e4.y, 0.f);
        m.z = fmaxf(x4.z + e4.z, 0.f);
        m.w = fmaxf(x4.w + e4.w, 0.f);
        float* p = M + dst * HID + lane * 4;
        asm volatile("red.global.add.v4.f32 [%0], {%1,%2,%3,%4};"
                     :: "l"(p), "f"(m.x), "f"(m.y), "f"(m.z), "f"(m.w) : "memory");
    }
}

// ---------------- 3xTF32 HMMA GEMM: C = relu(A @ W + bias) ----------------
// B fragments from global fragment-major layout (L1/L2 resident, LDG.128).
// A: raw cp.async double-buffered K=32 chunks in smem; hi/lo split in registers.
// Block 512 thr, CTA tile 256x128, warp grid 8Mx2N, warp tile 32x64.
#define MTILE 256
#define RS 36
#define RAW_WORDS (MTILE * RS)
#define STAT_OFF (2 * RAW_WORDS)
#define SMEM_GEMM ((STAT_OFF + 256) * 4)

template <bool STATS>
__global__ void __launch_bounds__(512, 1)
gemm_mma_kernel(const float* __restrict__ A, const uint4* __restrict__ Wf,
                const float* __restrict__ bias, float* __restrict__ C) {
    extern __shared__ char smem[];
    float* raw = (float*)smem;
    float* ssum = (float*)smem + STAT_OFF;
    float* ssq = ssum + 128;

    uint32_t rawAddr;
    asm("{ .reg .u64 t; cvta.to.shared.u64 t, %1; cvt.u32.u64 %0, t; }"
        : "=r"(rawAddr) : "l"(smem));

    int tid = threadIdx.x, wid = tid >> 5, lane = tid & 31;
    int wm = wid & 7, wn = wid >> 3;
    int g = lane >> 2, tg = lane & 3;
    int rowBase = blockIdx.x * MTILE;

    if (STATS && tid < 256) ssum[tid] = 0.f;

    // issue a K=32 chunk of A via cp.async (2048 x 16B)
    auto issue_chunk = [&](int chunk, int buf) {
#pragma unroll
        for (int j = 0; j < 4; j++) {
            int i = tid + j * 512;
            int r = i >> 3, q = i & 7;
            int grow = rowBase + r;
            const float* src = A + (size_t)min(grow, NN - 1) * HID + chunk * 32 + q * 4;
            uint32_t dst = rawAddr + (uint32_t)(buf * RAW_WORDS + r * RS + q * 4) * 4u;
            int sz = (grow < NN) ? 16 : 0;
            asm volatile("cp.async.cg.shared.global [%0], [%1], 16, %2;"
                         :: "r"(dst), "l"(src), "r"(sz));
        }
        asm volatile("cp.async.commit_group;");
    };
    issue_chunk(0, 0);
    issue_chunk(1, 1);

    float acc[2][8][4];
#pragma unroll
    for (int mt = 0; mt < 2; mt++)
#pragma unroll
        for (int nt = 0; nt < 8; nt++)
#pragma unroll
            for (int c = 0; c < 4; c++) acc[mt][nt][c] = 0.f;

    // per-warp base into fragment array: frag index = (kstep*16 + wn*8 + nt)*32 + lane
    const uint4* wfw = Wf + (size_t)(wn * 8) * 32 + lane;

#pragma unroll
    for (int chunk = 0; chunk < 4; chunk++) {
        if (chunk < 3) asm volatile("cp.async.wait_group 1;" ::: "memory");
        else           asm volatile("cp.async.wait_group 0;" ::: "memory");
        __syncthreads();
        const float* rb = raw + (chunk & 1) * RAW_WORDS;

#pragma unroll
        for (int ks = 0; ks < 4; ks++) {
            int k0 = ks * 8;
            int kstep = chunk * 4 + ks;
            const uint4* wfk = wfw + (size_t)kstep * 16 * 32;

            uint32_t afH[2][4], afL[2][4];
#pragma unroll
            for (int mt = 0; mt < 2; mt++) {
                int r = wm * 32 + mt * 16 + g;
                float v0 = rb[r * RS + k0 + tg];
                float v1 = rb[(r + 8) * RS + k0 + tg];
                float v2 = rb[r * RS + k0 + tg + 4];
                float v3 = rb[(r + 8) * RS + k0 + tg + 4];
                split_tf32(v0, afH[mt][0], afL[mt][0]);
                split_tf32(v1, afH[mt][1], afL[mt][1]);
                split_tf32(v2, afH[mt][2], afL[mt][2]);
                split_tf32(v3, afH[mt][3], afL[mt][3]);
            }
#pragma unroll
            for (int hb = 0; hb < 2; hb++) {
                uint4 bf[4];
#pragma unroll
                for (int q = 0; q < 4; q++)
                    bf[q] = __ldg(wfk + (hb * 4 + q) * 32);
#pragma unroll
                for (int mt = 0; mt < 2; mt++)
#pragma unroll
                    for (int q = 0; q < 4; q++) {
                        int nt = hb * 4 + q;
                        uint32_t bh[2] = {bf[q].x, bf[q].y};
                        uint32_t bl[2] = {bf[q].z, bf[q].w};
                        MMA_TF32(acc[mt][nt], afH[mt], bl);
                        MMA_TF32(acc[mt][nt], afL[mt], bh);
                        MMA_TF32(acc[mt][nt], afH[mt], bh);
                    }
            }
        }
        __syncthreads();
        if (chunk < 2) issue_chunk(chunk + 2, chunk & 1);
    }

    // epilogue: bias + relu, stores, optional column stats
#pragma unroll
    for (int nt = 0; nt < 8; nt++) {
        int col = wn * 64 + nt * 8 + tg * 2;
        float2 bv = __ldg((const float2*)(bias + col));
        float s0 = 0.f, s1 = 0.f, q0 = 0.f, q1 = 0.f;
#pragma unroll
        for (int mt = 0; mt < 2; mt++) {
            int r0 = rowBase + wm * 32 + mt * 16 + g;
            float2 oa, ob;
            oa.x = fmaxf(acc[mt][nt][0] + bv.x, 0.f);
            oa.y = fmaxf(acc[mt][nt][1] + bv.y, 0.f);
            ob.x = fmaxf(acc[mt][nt][2] + bv.x, 0.f);
            ob.y = fmaxf(acc[mt][nt][3] + bv.y, 0.f);
            if (r0 < NN) {
                *(float2*)(C + r0 * HID + col) = oa;
                if (STATS) { s0 += oa.x; q0 += oa.x * oa.x; s1 += oa.y; q1 += oa.y * oa.y; }
            }
            if (r0 + 8 < NN) {
                *(float2*)(C + (r0 + 8) * HID + col) = ob;
                if (STATS) { s0 += ob.x; q0 += ob.x * ob.x; s1 += ob.y; q1 += ob.y * ob.y; }
            }
        }
        if (STATS) {
#pragma unroll
            for (int m = 16; m >= 4; m >>= 1) {
                s0 += __shfl_xor_sync(0xffffffff, s0, m);
                s1 += __shfl_xor_sync(0xffffffff, s1, m);
                q0 += __shfl_xor_sync(0xffffffff, q0, m);
                q1 += __shfl_xor_sync(0xffffffff, q1, m);
            }
            if (lane < 4) {
                int c0 = wn * 64 + nt * 8 + lane * 2;
                atomicAdd(&ssum[c0], s0);
                atomicAdd(&ssum[c0 + 1], s1);
                atomicAdd(&ssq[c0], q0);
                atomicAdd(&ssq[c0 + 1], q1);
            }
        }
    }
    if (STATS) {
        __syncthreads();
        if (tid < 128) {
            atomicAdd(&g_sum[tid], (double)ssum[tid]);
            atomicAdd(&g_sumsq[tid], (double)ssq[tid]);
        }
    }
}

// ---------------- finalize: scale/shift from stats; reset accumulators ----------------
__global__ void finalize_kernel(const float* __restrict__ gw, const float* __restrict__ bw) {
    int c = threadIdx.x;
    double mu = g_sum[c] / (double)NN;
    double var = g_sumsq[c] / (double)NN - mu * mu;
    float sc = (float)((double)gw[c] * rsqrt(var + 1e-5));
    g_scale[c] = sc;
    g_shift[c] = bw[c] - (float)mu * sc;
    g_sum[c] = 0.0;
    g_sumsq[c] = 0.0;
}

// ---------------- pooling (applies final norm inline) ----------------
__global__ void zero_out_kernel(float* out) {
    int i = blockIdx.x * blockDim.x + threadIdx.x;
    if (i < NG * HID) out[i] = 0.f;
}

__global__ void pool_kernel(const float* __restrict__ R, const int* __restrict__ batch,
                            float* __restrict__ out) {
    int warp = (blockIdx.x * blockDim.x + threadIdx.x) >> 5;
    int lane = threadIdx.x & 31;
    if (warp >= NN) return;
    float4 sc = *(const float4*)(g_scale + lane * 4);
    float4 sh = *(const float4*)(g_shift + lane * 4);
    int g = __ldg(batch + warp);
    float4 v = __ldg((const float4*)(R + warp * HID) + lane);
    v.x = fmaf(v.x, sc.x, sh.x);
    v.y = fmaf(v.y, sc.y, sh.y);
    v.z = fmaf(v.z, sc.z, sh.z);
    v.w = fmaf(v.w, sc.w, sh.w);
    float* p = out + g * HID + lane * 4;
    asm volatile("red.global.add.v4.f32 [%0], {%1,%2,%3,%4};"
                 :: "l"(p), "f"(v.x), "f"(v.y), "f"(v.z), "f"(v.w) : "memory");
}

// ---------------- host ----------------
extern "C" void kernel_launch(void* const* d_in, const int* in_sizes, int n_in,
                              void* d_out, int out_size) {
    const int*   x_idx      = (const int*)d_in[0];
    const int*   edge_index = (const int*)d_in[1];
    const int*   edge_attr  = (const int*)d_in[2];
    const int*   batch      = (const int*)d_in[3];
    const float* node_emb   = (const float*)d_in[4];
    const float* edge_emb   = (const float*)d_in[5];
    const float* W1         = (const float*)d_in[6];
    const float* b1         = (const float*)d_in[7];
    const float* W2         = (const float*)d_in[8];
    const float* b2         = (const float*)d_in[9];
    const float* bn_g       = (const float*)d_in[10];
    const float* bn_b       = (const float*)d_in[11];
    float* out = (float*)d_out;

    cudaFuncSetAttribute(gemm_mma_kernel<false>,
                         cudaFuncAttributeMaxDynamicSharedMemorySize, SMEM_GEMM);
    cudaFuncSetAttribute(gemm_mma_kernel<true>,
                         cudaFuncAttributeMaxDynamicSharedMemorySize, SMEM_GEMM);

    float *Xn, *M, *Ap, *R;
    uint4* Wf;
    cudaGetSymbolAddress((void**)&Xn, g_Xn);
    cudaGetSymbolAddress((void**)&M, g_M);
    cudaGetSymbolAddress((void**)&Ap, g_A);
    cudaGetSymbolAddress((void**)&R, g_R);
    cudaGetSymbolAddress((void**)&Wf, g_Wf);

    int nf4 = NN * (HID / 4);
    int cpBlocks = (nf4 + 255) / 256;
    int gemmBlocks = (NN + MTILE - 1) / MTILE;

    prep_w_kernel<<<(4 * HID * HID + 255) / 256, 256>>>(W1, W2);
    embed_kernel<<<cpBlocks, 256>>>(x_idx, node_emb);

    for (int l = 0; l < NL; l++) {
        if (l > 0) init_kernel<<<cpBlocks, 256>>>(R);
        edge_kernel<<<NE / 64, 256>>>(Xn, M, edge_index, edge_attr, edge_emb);
        gemm_mma_kernel<false><<<gemmBlocks, 512, SMEM_GEMM>>>(
            M, Wf + (size_t)(l * 2 + 0) * 8192, b1 + l * HID, Ap);
        gemm_mma_kernel<true><<<gemmBlocks, 512, SMEM_GEMM>>>(
            Ap, Wf + (size_t)(l * 2 + 1) * 8192, b2 + l * HID, R);
        finalize_kernel<<<1, 128>>>(bn_g + l * HID, bn_b + l * HID);
    }

    zero_out_kernel<<<(NG * HID + 255) / 256, 256>>>(out);
    pool_kernel<<<NN * 32 / 256, 256>>>(R, batch, out);
}

// round 9
// speedup vs baseline: 1.3564x; 1.0419x over previous
#include <cuda_runtime.h>
#include <cstdint>

#define HID 128
#define NN 50000
#define NE 800000
#define NG 64
#define NL 2

// ---------------- scratch (static device allocations) ----------------
__device__ __align__(16) float g_Xn[NN * HID];   // normed layer input
__device__ __align__(16) float g_M[NN * HID];    // Xn + aggregation (gemm1 input)
__device__ __align__(16) float g_A[NN * HID];    // gemm1 output
__device__ __align__(16) float g_R[NN * HID];    // gemm2 raw output
__device__ __align__(16) uint32_t g_Wf[4 * 32768]; // fragment-major hi/lo weights
__device__ int g_cnt[NN];
__device__ int g_off[NN + 1];
__device__ int g_cur[NN];
__device__ int g_list[NE];
__device__ double g_sum[HID];
__device__ double g_sumsq[HID];
__device__ __align__(16) float g_scale[HID];
__device__ __align__(16) float g_shift[HID];

__device__ __forceinline__ uint32_t f2tf32(float v) {
    uint32_t o;
    asm("cvt.rna.tf32.f32 %0, %1;" : "=r"(o) : "f"(v));
    return o;
}
__device__ __forceinline__ void split_tf32(float v, uint32_t& h, uint32_t& l) {
    h = f2tf32(v);
    l = f2tf32(v - __uint_as_float(h));
}

#define MMA_TF32(d, a, b) \
    asm volatile("mma.sync.aligned.m16n8k8.row.col.f32.tf32.tf32.f32 " \
        "{%0,%1,%2,%3}, {%4,%5,%6,%7}, {%8,%9}, {%0,%1,%2,%3};" \
        : "+f"((d)[0]), "+f"((d)[1]), "+f"((d)[2]), "+f"((d)[3]) \
        : "r"((a)[0]), "r"((a)[1]), "r"((a)[2]), "r"((a)[3]), \
          "r"((b)[0]), "r"((b)[1]))

// ---------------- weight prep: fragment-major hi/lo layout ----------------
__global__ void prep_w_kernel(const float* __restrict__ W1, const float* __restrict__ W2) {
    int i = blockIdx.x * blockDim.x + threadIdx.x;
    if (i >= 4 * HID * HID) return;
    int w = i >> 14;
    int k = (i >> 7) & 127;
    int n = i & 127;
    int l = w >> 1;
    const float* W = (w & 1) ? W2 : W1;
    float v = __ldg(W + l * HID * HID + k * HID + n);
    uint32_t h, lo;
    split_tf32(v, h, lo);
    int lane = (n & 7) * 4 + (k & 3);
    int word = (k >> 2) & 1;
    int base4 = ((w * 256 + (k >> 3) * 16 + (n >> 3)) * 32 + lane) * 4;
    g_Wf[base4 + word] = h;
    g_Wf[base4 + 2 + word] = lo;
}

// ---------------- CSR build (once; graph is layer-invariant) ----------------
__global__ void zero_cnt_kernel() {
    int i = blockIdx.x * blockDim.x + threadIdx.x;
    if (i < NN) g_cnt[i] = 0;
}
__global__ void hist_kernel(const int* __restrict__ ei) {
    int e = blockIdx.x * blockDim.x + threadIdx.x;
    if (e < NE) atomicAdd(&g_cnt[__ldg(ei + NE + e)], 1);
}
__global__ void scan_kernel() {
    __shared__ int part[1024];
    int tid = threadIdx.x;
    const int CH = (NN + 1023) / 1024;
    int base = tid * CH;
    int s = 0;
    for (int j = 0; j < CH; j++) {
        int i = base + j;
        if (i < NN) s += g_cnt[i];
    }
    part[tid] = s;
    __syncthreads();
    for (int d = 1; d < 1024; d <<= 1) {
        int v = (tid >= d) ? part[tid - d] : 0;
        __syncthreads();
        part[tid] += v;
        __syncthreads();
    }
    int run = (tid > 0) ? part[tid - 1] : 0;
    for (int j = 0; j < CH; j++) {
        int i = base + j;
        if (i < NN) {
            int c = g_cnt[i];
            g_off[i] = run;
            g_cur[i] = run;
            run += c;
        }
    }
    if (tid == 0) g_off[NN] = NE;
}
__global__ void scatter_kernel(const int* __restrict__ ei, const int* __restrict__ ea) {
    int e = blockIdx.x * blockDim.x + threadIdx.x;
    if (e >= NE) return;
    int src = __ldg(ei + e);
    int dst = __ldg(ei + NE + e);
    int attr = __ldg(ea + e);
    int p = atomicAdd(&g_cur[dst], 1);
    g_list[p] = (src << 2) | attr;
}

// ---------------- embed: Xn = node_emb[x_idx] ----------------
__global__ void embed_kernel(const int* __restrict__ xi, const float* __restrict__ nemb) {
    int i = blockIdx.x * blockDim.x + threadIdx.x;
    if (i >= NN * (HID / 4)) return;
    int n = i >> 5;
    int c = i & 31;
    ((float4*)g_Xn)[i] = __ldg((const float4*)(nemb + xi[n] * HID) + c);
}

// ---------------- init (between layers): Xn = norm(R) ----------------
__global__ void init_kernel(const float* __restrict__ R) {
    int i = blockIdx.x * blockDim.x + threadIdx.x;
    if (i >= NN * (HID / 4)) return;
    int c = i & 31;
    float4 v = __ldg((const float4*)R + i);
    float4 sc = *(const float4*)(g_scale + c * 4);
    float4 sh = *(const float4*)(g_shift + c * 4);
    v.x = fmaf(v.x, sc.x, sh.x);
    v.y = fmaf(v.y, sc.y, sh.y);
    v.z = fmaf(v.z, sc.z, sh.z);
    v.w = fmaf(v.w, sc.w, sh.w);
    ((float4*)g_Xn)[i] = v;
}

// ---------------- aggregate: M[n] = Xn[n] + sum_{e->n} relu(Xn[src]+eemb[attr]) ----------------
__global__ void aggregate_kernel(const float* __restrict__ Xn, float* __restrict__ M,
                                 const float* __restrict__ eemb) {
    int node = (blockIdx.x * blockDim.x + threadIdx.x) >> 5;
    int lane = threadIdx.x & 31;
    if (node >= NN) return;
    int s = g_off[node];
    int e = g_off[node + 1];
    float4 acc = __ldg((const float4*)(Xn + node * HID) + lane);
    for (int i = s; i < e; i++) {
        int pk = __ldg(g_list + i);
        int src = pk >> 2, attr = pk & 3;
        float4 x4 = __ldg((const float4*)(Xn + src * HID) + lane);
        float4 e4 = __ldg((const float4*)(eemb + attr * HID) + lane);
        acc.x += fmaxf(x4.x + e4.x, 0.f);
        acc.y += fmaxf(x4.y + e4.y, 0.f);
        acc.z += fmaxf(x4.z + e4.z, 0.f);
        acc.w += fmaxf(x4.w + e4.w, 0.f);
    }
    *((float4*)(M + node * HID) + lane) = acc;
}

// ---------------- 3xTF32 HMMA GEMM: C = relu(A @ W + bias) ----------------
// B fragments via LDG.128 from fragment-major global layout (L1/L2 resident).
// A: raw cp.async double-buffered K=32 chunks in smem; hi/lo split in registers.
// Block 256 thr, CTA tile 128x128, warp grid 4Mx2N, warp tile 32x64, 2 CTA/SM.
#define MTILE 128
#define RS 36
#define RAW_WORDS (MTILE * RS)
#define STAT_OFF (2 * RAW_WORDS)
#define SMEM_GEMM ((STAT_OFF + 256) * 4)

template <bool STATS>
__global__ void __launch_bounds__(256, 2)
gemm_mma_kernel(const float* __restrict__ A, const uint4* __restrict__ Wf,
                const float* __restrict__ bias, float* __restrict__ C) {
    extern __shared__ char smem[];
    float* raw = (float*)smem;
    float* ssum = (float*)smem + STAT_OFF;
    float* ssq = ssum + 128;

    uint32_t rawAddr;
    asm("{ .reg .u64 t; cvta.to.shared.u64 t, %1; cvt.u32.u64 %0, t; }"
        : "=r"(rawAddr) : "l"(smem));

    int tid = threadIdx.x, wid = tid >> 5, lane = tid & 31;
    int wm = wid & 3, wn = wid >> 2;
    int g = lane >> 2, tg = lane & 3;
    int rowBase = blockIdx.x * MTILE;

    if (STATS) ssum[tid] = 0.f;   // 256 threads cover ssum+ssq

    auto issue_chunk = [&](int chunk, int buf) {
#pragma unroll
        for (int j = 0; j < 4; j++) {
            int i = tid + j * 256;
            int r = i >> 3, q = i & 7;
            int grow = rowBase + r;
            const float* src = A + (size_t)min(grow, NN - 1) * HID + chunk * 32 + q * 4;
            uint32_t dst = rawAddr + (uint32_t)(buf * RAW_WORDS + r * RS + q * 4) * 4u;
            int sz = (grow < NN) ? 16 : 0;
            asm volatile("cp.async.cg.shared.global [%0], [%1], 16, %2;"
                         :: "r"(dst), "l"(src), "r"(sz));
        }
        asm volatile("cp.async.commit_group;");
    };
    issue_chunk(0, 0);
    issue_chunk(1, 1);

    float acc[2][8][4];
#pragma unroll
    for (int mt = 0; mt < 2; mt++)
#pragma unroll
        for (int nt = 0; nt < 8; nt++)
#pragma unroll
            for (int c = 0; c < 4; c++) acc[mt][nt][c] = 0.f;

    const uint4* wfw = Wf + (size_t)(wn * 8) * 32 + lane;

#pragma unroll
    for (int chunk = 0; chunk < 4; chunk++) {
        if (chunk < 3) asm volatile("cp.async.wait_group 1;" ::: "memory");
        else           asm volatile("cp.async.wait_group 0;" ::: "memory");
        __syncthreads();
        const float* rb = raw + (chunk & 1) * RAW_WORDS;

#pragma unroll
        for (int ks = 0; ks < 4; ks++) {
            int k0 = ks * 8;
            int kstep = chunk * 4 + ks;
            const uint4* wfk = wfw + (size_t)kstep * 16 * 32;

            uint32_t afH[2][4], afL[2][4];
#pragma unroll
            for (int mt = 0; mt < 2; mt++) {
                int r = wm * 32 + mt * 16 + g;
                float v0 = rb[r * RS + k0 + tg];
                float v1 = rb[(r + 8) * RS + k0 + tg];
                float v2 = rb[r * RS + k0 + tg + 4];
                float v3 = rb[(r + 8) * RS + k0 + tg + 4];
                split_tf32(v0, afH[mt][0], afL[mt][0]);
                split_tf32(v1, afH[mt][1], afL[mt][1]);
                split_tf32(v2, afH[mt][2], afL[mt][2]);
                split_tf32(v3, afH[mt][3], afL[mt][3]);
            }
#pragma unroll
            for (int hb = 0; hb < 2; hb++) {
                uint4 bf[4];
#pragma unroll
                for (int q = 0; q < 4; q++)
                    bf[q] = __ldg(wfk + (hb * 4 + q) * 32);
#pragma unroll
                for (int mt = 0; mt < 2; mt++)
#pragma unroll
                    for (int q = 0; q < 4; q++) {
                        int nt = hb * 4 + q;
                        uint32_t bh[2] = {bf[q].x, bf[q].y};
                        uint32_t bl[2] = {bf[q].z, bf[q].w};
                        MMA_TF32(acc[mt][nt], afH[mt], bl);
                        MMA_TF32(acc[mt][nt], afL[mt], bh);
                        MMA_TF32(acc[mt][nt], afH[mt], bh);
                    }
            }
        }
        __syncthreads();
        if (chunk < 2) issue_chunk(chunk + 2, chunk & 1);
    }

    // epilogue: bias + relu, stores, optional column stats
#pragma unroll
    for (int nt = 0; nt < 8; nt++) {
        int col = wn * 64 + nt * 8 + tg * 2;
        float2 bv = __ldg((const float2*)(bias + col));
        float s0 = 0.f, s1 = 0.f, q0 = 0.f, q1 = 0.f;
#pragma unroll
        for (int mt = 0; mt < 2; mt++) {
            int r0 = rowBase + wm * 32 + mt * 16 + g;
            float2 oa, ob;
            oa.x = fmaxf(acc[mt][nt][0] + bv.x, 0.f);
            oa.y = fmaxf(acc[mt][nt][1] + bv.y, 0.f);
            ob.x = fmaxf(acc[mt][nt][2] + bv.x, 0.f);
            ob.y = fmaxf(acc[mt][nt][3] + bv.y, 0.f);
            if (r0 < NN) {
                *(float2*)(C + r0 * HID + col) = oa;
                if (STATS) { s0 += oa.x; q0 += oa.x * oa.x; s1 += oa.y; q1 += oa.y * oa.y; }
            }
            if (r0 + 8 < NN) {
                *(float2*)(C + (r0 + 8) * HID + col) = ob;
                if (STATS) { s0 += ob.x; q0 += ob.x * ob.x; s1 += ob.y; q1 += ob.y * ob.y; }
            }
        }
        if (STATS) {
#pragma unroll
            for (int m = 16; m >= 4; m >>= 1) {
                s0 += __shfl_xor_sync(0xffffffff, s0, m);
                s1 += __shfl_xor_sync(0xffffffff, s1, m);
                q0 += __shfl_xor_sync(0xffffffff, q0, m);
                q1 += __shfl_xor_sync(0xffffffff, q1, m);
            }
            if (lane < 4) {
                int c0 = wn * 64 + nt * 8 + lane * 2;
                atomicAdd(&ssum[c0], s0);
                atomicAdd(&ssum[c0 + 1], s1);
                atomicAdd(&ssq[c0], q0);
                atomicAdd(&ssq[c0 + 1], q1);
            }
        }
    }
    if (STATS) {
        __syncthreads();
        if (tid < 128) {
            atomicAdd(&g_sum[tid], (double)ssum[tid]);
            atomicAdd(&g_sumsq[tid], (double)ssq[tid]);
        }
    }
}

// ---------------- finalize: scale/shift from stats; reset accumulators ----------------
__global__ void finalize_kernel(const float* __restrict__ gw, const float* __restrict__ bw) {
    int c = threadIdx.x;
    double mu = g_sum[c] / (double)NN;
    double var = g_sumsq[c] / (double)NN - mu * mu;
    float sc = (float)((double)gw[c] * rsqrt(var + 1e-5));
    g_scale[c] = sc;
    g_shift[c] = bw[c] - (float)mu * sc;
    g_sum[c] = 0.0;
    g_sumsq[c] = 0.0;
}

// ---------------- pooling (applies final norm inline) ----------------
__global__ void zero_out_kernel(float* out) {
    int i = blockIdx.x * blockDim.x + threadIdx.x;
    if (i < NG * HID) out[i] = 0.f;
}

__global__ void pool_kernel(const float* __restrict__ R, const int* __restrict__ batch,
                            float* __restrict__ out) {
    int warp = (blockIdx.x * blockDim.x + threadIdx.x) >> 5;
    int lane = threadIdx.x & 31;
    if (warp >= NN) return;
    float4 sc = *(const float4*)(g_scale + lane * 4);
    float4 sh = *(const float4*)(g_shift + lane * 4);
    int g = __ldg(batch + warp);
    float4 v = __ldg((const float4*)(R + warp * HID) + lane);
    v.x = fmaf(v.x, sc.x, sh.x);
    v.y = fmaf(v.y, sc.y, sh.y);
    v.z = fmaf(v.z, sc.z, sh.z);
    v.w = fmaf(v.w, sc.w, sh.w);
    float* p = out + g * HID + lane * 4;
    asm volatile("red.global.add.v4.f32 [%0], {%1,%2,%3,%4};"
                 :: "l"(p), "f"(v.x), "f"(v.y), "f"(v.z), "f"(v.w) : "memory");
}

// ---------------- host ----------------
extern "C" void kernel_launch(void* const* d_in, const int* in_sizes, int n_in,
                              void* d_out, int out_size) {
    const int*   x_idx      = (const int*)d_in[0];
    const int*   edge_index = (const int*)d_in[1];
    const int*   edge_attr  = (const int*)d_in[2];
    const int*   batch      = (const int*)d_in[3];
    const float* node_emb   = (const float*)d_in[4];
    const float* edge_emb   = (const float*)d_in[5];
    const float* W1         = (const float*)d_in[6];
    const float* b1         = (const float*)d_in[7];
    const float* W2         = (const float*)d_in[8];
    const float* b2         = (const float*)d_in[9];
    const float* bn_g       = (const float*)d_in[10];
    const float* bn_b       = (const float*)d_in[11];
    float* out = (float*)d_out;

    cudaFuncSetAttribute(gemm_mma_kernel<false>,
                         cudaFuncAttributeMaxDynamicSharedMemorySize, SMEM_GEMM);
    cudaFuncSetAttribute(gemm_mma_kernel<true>,
                         cudaFuncAttributeMaxDynamicSharedMemorySize, SMEM_GEMM);

    float *Xn, *M, *Ap, *R;
    uint4* Wf;
    cudaGetSymbolAddress((void**)&Xn, g_Xn);
    cudaGetSymbolAddress((void**)&M, g_M);
    cudaGetSymbolAddress((void**)&Ap, g_A);
    cudaGetSymbolAddress((void**)&R, g_R);
    cudaGetSymbolAddress((void**)&Wf, g_Wf);

    int nf4 = NN * (HID / 4);
    int cpBlocks = (nf4 + 255) / 256;
    int gemmBlocks = (NN + MTILE - 1) / MTILE;

    prep_w_kernel<<<(4 * HID * HID + 255) / 256, 256>>>(W1, W2);
    zero_cnt_kernel<<<(NN + 255) / 256, 256>>>();
    hist_kernel<<<(NE + 255) / 256, 256>>>(edge_index);
    scan_kernel<<<1, 1024>>>();
    scatter_kernel<<<(NE + 255) / 256, 256>>>(edge_index, edge_attr);
    embed_kernel<<<cpBlocks, 256>>>(x_idx, node_emb);

    for (int l = 0; l < NL; l++) {
        if (l > 0) init_kernel<<<cpBlocks, 256>>>(R);
        aggregate_kernel<<<(NN * 32 + 255) / 256, 256>>>(Xn, M, edge_emb);
        gemm_mma_kernel<false><<<gemmBlocks, 256, SMEM_GEMM>>>(
            M, Wf + (size_t)(l * 2 + 0) * 8192, b1 + l * HID, Ap);
        gemm_mma_kernel<true><<<gemmBlocks, 256, SMEM_GEMM>>>(
            Ap, Wf + (size_t)(l * 2 + 1) * 8192, b2 + l * HID, R);
        finalize_kernel<<<1, 128>>>(bn_g + l * HID, bn_b + l * HID);
    }

    zero_out_kernel<<<(NG * HID + 255) / 256, 256>>>(out);
    pool_kernel<<<NN * 32 / 256, 256>>>(R, batch, out);
}

// round 10
// speedup vs baseline: 1.6864x; 1.2434x over previous
#include <cuda_runtime.h>
#include <cstdint>

#define HID 128
#define NN 50000
#define NE 800000
#define NG 64
#define NL 2

#define SCAN_B 512
#define SCAN_BLOCKS ((NN + SCAN_B - 1) / SCAN_B)   // 98

// ---------------- scratch (static device allocations) ----------------
__device__ __align__(16) float g_Xn[NN * HID];   // normed layer input
__device__ __align__(16) float g_M[NN * HID];    // Xn + aggregation (gemm1 input)
__device__ __align__(16) float g_A[NN * HID];    // gemm1 output
__device__ __align__(16) float g_R[NN * HID];    // gemm2 raw output
__device__ __align__(16) uint32_t g_Wf[4 * 32768]; // fragment-major hi/lo weights
__device__ int g_cnt[NN];
__device__ int g_off[NN + 1];
__device__ int g_cur[NN];
__device__ int g_bsum[SCAN_BLOCKS];
__device__ int g_boff[SCAN_BLOCKS];
__device__ int g_list[NE];
__device__ double g_sum[HID];
__device__ double g_sumsq[HID];
__device__ __align__(16) float g_scale[HID];
__device__ __align__(16) float g_shift[HID];

__device__ __forceinline__ uint32_t f2tf32(float v) {
    uint32_t o;
    asm("cvt.rna.tf32.f32 %0, %1;" : "=r"(o) : "f"(v));
    return o;
}
__device__ __forceinline__ void split_tf32(float v, uint32_t& h, uint32_t& l) {
    h = f2tf32(v);
    l = f2tf32(v - __uint_as_float(h));
}

#define MMA_TF32(d, a, b) \
    asm volatile("mma.sync.aligned.m16n8k8.row.col.f32.tf32.tf32.f32 " \
        "{%0,%1,%2,%3}, {%4,%5,%6,%7}, {%8,%9}, {%0,%1,%2,%3};" \
        : "+f"((d)[0]), "+f"((d)[1]), "+f"((d)[2]), "+f"((d)[3]) \
        : "r"((a)[0]), "r"((a)[1]), "r"((a)[2]), "r"((a)[3]), \
          "r"((b)[0]), "r"((b)[1]))

// ---------------- weight prep: fragment-major hi/lo layout ----------------
__global__ void prep_w_kernel(const float* __restrict__ W1, const float* __restrict__ W2) {
    int i = blockIdx.x * blockDim.x + threadIdx.x;
    if (i >= 4 * HID * HID) return;
    int w = i >> 14;
    int k = (i >> 7) & 127;
    int n = i & 127;
    int l = w >> 1;
    const float* W = (w & 1) ? W2 : W1;
    float v = __ldg(W + l * HID * HID + k * HID + n);
    uint32_t h, lo;
    split_tf32(v, h, lo);
    int lane = (n & 7) * 4 + (k & 3);
    int word = (k >> 2) & 1;
    int base4 = ((w * 256 + (k >> 3) * 16 + (n >> 3)) * 32 + lane) * 4;
    g_Wf[base4 + word] = h;
    g_Wf[base4 + 2 + word] = lo;
}

// ---------------- CSR build (once per call; graph is layer-invariant) ----------------
__global__ void zero_cnt_kernel() {
    int i = blockIdx.x * blockDim.x + threadIdx.x;
    if (i < NN) g_cnt[i] = 0;
}
__global__ void hist_kernel(const int* __restrict__ ei) {
    int e = blockIdx.x * blockDim.x + threadIdx.x;
    if (e < NE) atomicAdd(&g_cnt[__ldg(ei + NE + e)], 1);
}
// phase 1: per-block exclusive scan + block totals
__global__ void scan1_kernel() {
    __shared__ int sh[SCAN_B];
    int tid = threadIdx.x;
    int i = blockIdx.x * SCAN_B + tid;
    int v = (i < NN) ? g_cnt[i] : 0;
    sh[tid] = v;
    __syncthreads();
#pragma unroll
    for (int d = 1; d < SCAN_B; d <<= 1) {
        int t = (tid >= d) ? sh[tid - d] : 0;
        __syncthreads();
        sh[tid] += t;
        __syncthreads();
    }
    if (i < NN) g_off[i] = sh[tid] - v;     // exclusive within block
    if (tid == SCAN_B - 1) g_bsum[blockIdx.x] = sh[tid];
}
// phase 2: scan the 98 block totals (single small block)
__global__ void scan2_kernel() {
    __shared__ int sh[128];
    int tid = threadIdx.x;
    int v = (tid < SCAN_BLOCKS) ? g_bsum[tid] : 0;
    sh[tid] = v;
    __syncthreads();
#pragma unroll
    for (int d = 1; d < 128; d <<= 1) {
        int t = (tid >= d) ? sh[tid - d] : 0;
        __syncthreads();
        sh[tid] += t;
        __syncthreads();
    }
    if (tid < SCAN_BLOCKS) g_boff[tid] = sh[tid] - v;
}
// phase 3: add block offsets, init cursors
__global__ void scan3_kernel() {
    int i = blockIdx.x * SCAN_B + threadIdx.x;
    if (i < NN) {
        int o = g_off[i] + g_boff[blockIdx.x];
        g_off[i] = o;
        g_cur[i] = o;
    }
    if (i == 0) g_off[NN] = NE;
}
__global__ void scatter_kernel(const int* __restrict__ ei, const int* __restrict__ ea) {
    int e = blockIdx.x * blockDim.x + threadIdx.x;
    if (e >= NE) return;
    int src = __ldg(ei + e);
    int dst = __ldg(ei + NE + e);
    int attr = __ldg(ea + e);
    int p = atomicAdd(&g_cur[dst], 1);
    g_list[p] = (src << 2) | attr;
}

// ---------------- embed: Xn = node_emb[x_idx] ----------------
__global__ void embed_kernel(const int* __restrict__ xi, const float* __restrict__ nemb) {
    int i = blockIdx.x * blockDim.x + threadIdx.x;
    if (i >= NN * (HID / 4)) return;
    int n = i >> 5;
    int c = i & 31;
    ((float4*)g_Xn)[i] = __ldg((const float4*)(nemb + xi[n] * HID) + c);
}

// ---------------- init (between layers): Xn = norm(R) ----------------
__global__ void init_kernel(const float* __restrict__ R) {
    int i = blockIdx.x * blockDim.x + threadIdx.x;
    if (i >= NN * (HID / 4)) return;
    int c = i & 31;
    float4 v = __ldg((const float4*)R + i);
    float4 sc = *(const float4*)(g_scale + c * 4);
    float4 sh = *(const float4*)(g_shift + c * 4);
    v.x = fmaf(v.x, sc.x, sh.x);
    v.y = fmaf(v.y, sc.y, sh.y);
    v.z = fmaf(v.z, sc.z, sh.z);
    v.w = fmaf(v.w, sc.w, sh.w);
    ((float4*)g_Xn)[i] = v;
}

// ---------------- aggregate: M[n] = Xn[n] + sum_{e->n} relu(Xn[src]+eemb[attr]) ----------------
__global__ void aggregate_kernel(const float* __restrict__ Xn, float* __restrict__ M,
                                 const float* __restrict__ eemb) {
    int node = (blockIdx.x * blockDim.x + threadIdx.x) >> 5;
    int lane = threadIdx.x & 31;
    if (node >= NN) return;
    int s = g_off[node];
    int e = g_off[node + 1];
    float4 acc = __ldg((const float4*)(Xn + node * HID) + lane);
    for (int i = s; i < e; i++) {
        int pk = __ldg(g_list + i);
        int src = pk >> 2, attr = pk & 3;
        float4 x4 = __ldg((const float4*)(Xn + src * HID) + lane);
        float4 e4 = __ldg((const float4*)(eemb + attr * HID) + lane);
        acc.x += fmaxf(x4.x + e4.x, 0.f);
        acc.y += fmaxf(x4.y + e4.y, 0.f);
        acc.z += fmaxf(x4.z + e4.z, 0.f);
        acc.w += fmaxf(x4.w + e4.w, 0.f);
    }
    *((float4*)(M + node * HID) + lane) = acc;
}

// ---------------- 3xTF32 HMMA GEMM: C = relu(A @ W + bias) ----------------
#define MTILE 128
#define RS 36
#define RAW_WORDS (MTILE * RS)
#define STAT_OFF (2 * RAW_WORDS)
#define SMEM_GEMM ((STAT_OFF + 256) * 4)

template <bool STATS>
__global__ void __launch_bounds__(256, 2)
gemm_mma_kernel(const float* __restrict__ A, const uint4* __restrict__ Wf,
                const float* __restrict__ bias, float* __restrict__ C) {
    extern __shared__ char smem[];
    float* raw = (float*)smem;
    float* ssum = (float*)smem + STAT_OFF;
    float* ssq = ssum + 128;

    uint32_t rawAddr;
    asm("{ .reg .u64 t; cvta.to.shared.u64 t, %1; cvt.u32.u64 %0, t; }"
        : "=r"(rawAddr) : "l"(smem));

    int tid = threadIdx.x, wid = tid >> 5, lane = tid & 31;
    int wm = wid & 3, wn = wid >> 2;
    int g = lane >> 2, tg = lane & 3;
    int rowBase = blockIdx.x * MTILE;

    if (STATS) ssum[tid] = 0.f;

    auto issue_chunk = [&](int chunk, int buf) {
#pragma unroll
        for (int j = 0; j < 4; j++) {
            int i = tid + j * 256;
            int r = i >> 3, q = i & 7;
            int grow = rowBase + r;
            const float* src = A + (size_t)min(grow, NN - 1) * HID + chunk * 32 + q * 4;
            uint32_t dst = rawAddr + (uint32_t)(buf * RAW_WORDS + r * RS + q * 4) * 4u;
            int sz = (grow < NN) ? 16 : 0;
            asm volatile("cp.async.cg.shared.global [%0], [%1], 16, %2;"
                         :: "r"(dst), "l"(src), "r"(sz));
        }
        asm volatile("cp.async.commit_group;");
    };
    issue_chunk(0, 0);
    issue_chunk(1, 1);

    float acc[2][8][4];
#pragma unroll
    for (int mt = 0; mt < 2; mt++)
#pragma unroll
        for (int nt = 0; nt < 8; nt++)
#pragma unroll
            for (int c = 0; c < 4; c++) acc[mt][nt][c] = 0.f;

    const uint4* wfw = Wf + (size_t)(wn * 8) * 32 + lane;

#pragma unroll
    for (int chunk = 0; chunk < 4; chunk++) {
        if (chunk < 3) asm volatile("cp.async.wait_group 1;" ::: "memory");
        else           asm volatile("cp.async.wait_group 0;" ::: "memory");
        __syncthreads();
        const float* rb = raw + (chunk & 1) * RAW_WORDS;

#pragma unroll
        for (int ks = 0; ks < 4; ks++) {
            int k0 = ks * 8;
            int kstep = chunk * 4 + ks;
            const uint4* wfk = wfw + (size_t)kstep * 16 * 32;

            uint32_t afH[2][4], afL[2][4];
#pragma unroll
            for (int mt = 0; mt < 2; mt++) {
                int r = wm * 32 + mt * 16 + g;
                float v0 = rb[r * RS + k0 + tg];
                float v1 = rb[(r + 8) * RS + k0 + tg];
                float v2 = rb[r * RS + k0 + tg + 4];
                float v3 = rb[(r + 8) * RS + k0 + tg + 4];
                split_tf32(v0, afH[mt][0], afL[mt][0]);
                split_tf32(v1, afH[mt][1], afL[mt][1]);
                split_tf32(v2, afH[mt][2], afL[mt][2]);
                split_tf32(v3, afH[mt][3], afL[mt][3]);
            }
#pragma unroll
            for (int hb = 0; hb < 2; hb++) {
                uint4 bf[4];
#pragma unroll
                for (int q = 0; q < 4; q++)
                    bf[q] = __ldg(wfk + (hb * 4 + q) * 32);
#pragma unroll
                for (int mt = 0; mt < 2; mt++)
#pragma unroll
                    for (int q = 0; q < 4; q++) {
                        int nt = hb * 4 + q;
                        uint32_t bh[2] = {bf[q].x, bf[q].y};
                        uint32_t bl[2] = {bf[q].z, bf[q].w};
                        MMA_TF32(acc[mt][nt], afH[mt], bl);
                        MMA_TF32(acc[mt][nt], afL[mt], bh);
                        MMA_TF32(acc[mt][nt], afH[mt], bh);
                    }
            }
        }
        __syncthreads();
        if (chunk < 2) issue_chunk(chunk + 2, chunk & 1);
    }

#pragma unroll
    for (int nt = 0; nt < 8; nt++) {
        int col = wn * 64 + nt * 8 + tg * 2;
        float2 bv = __ldg((const float2*)(bias + col));
        float s0 = 0.f, s1 = 0.f, q0 = 0.f, q1 = 0.f;
#pragma unroll
        for (int mt = 0; mt < 2; mt++) {
            int r0 = rowBase + wm * 32 + mt * 16 + g;
            float2 oa, ob;
            oa.x = fmaxf(acc[mt][nt][0] + bv.x, 0.f);
            oa.y = fmaxf(acc[mt][nt][1] + bv.y, 0.f);
            ob.x = fmaxf(acc[mt][nt][2] + bv.x, 0.f);
            ob.y = fmaxf(acc[mt][nt][3] + bv.y, 0.f);
            if (r0 < NN) {
                *(float2*)(C + r0 * HID + col) = oa;
                if (STATS) { s0 += oa.x; q0 += oa.x * oa.x; s1 += oa.y; q1 += oa.y * oa.y; }
            }
            if (r0 + 8 < NN) {
                *(float2*)(C + (r0 + 8) * HID + col) = ob;
                if (STATS) { s0 += ob.x; q0 += ob.x * ob.x; s1 += ob.y; q1 += ob.y * ob.y; }
            }
        }
        if (STATS) {
#pragma unroll
            for (int m = 16; m >= 4; m >>= 1) {
                s0 += __shfl_xor_sync(0xffffffff, s0, m);
                s1 += __shfl_xor_sync(0xffffffff, s1, m);
                q0 += __shfl_xor_sync(0xffffffff, q0, m);
                q1 += __shfl_xor_sync(0xffffffff, q1, m);
            }
            if (lane < 4) {
                int c0 = wn * 64 + nt * 8 + lane * 2;
                atomicAdd(&ssum[c0], s0);
                atomicAdd(&ssum[c0 + 1], s1);
                atomicAdd(&ssq[c0], q0);
                atomicAdd(&ssq[c0 + 1], q1);
            }
        }
    }
    if (STATS) {
        __syncthreads();
        if (tid < 128) {
            atomicAdd(&g_sum[tid], (double)ssum[tid]);
            atomicAdd(&g_sumsq[tid], (double)ssq[tid]);
        }
    }
}

// ---------------- finalize: scale/shift from stats; reset accumulators ----------------
__global__ void finalize_kernel(const float* __restrict__ gw, const float* __restrict__ bw) {
    int c = threadIdx.x;
    double mu = g_sum[c] / (double)NN;
    double var = g_sumsq[c] / (double)NN - mu * mu;
    float sc = (float)((double)gw[c] * rsqrt(var + 1e-5));
    g_scale[c] = sc;
    g_shift[c] = bw[c] - (float)mu * sc;
    g_sum[c] = 0.0;
    g_sumsq[c] = 0.0;
}

// ---------------- pooling (applies final norm inline) ----------------
__global__ void zero_out_kernel(float* out) {
    int i = blockIdx.x * blockDim.x + threadIdx.x;
    if (i < NG * HID) out[i] = 0.f;
}

__global__ void pool_kernel(const float* __restrict__ R, const int* __restrict__ batch,
                            float* __restrict__ out) {
    int warp = (blockIdx.x * blockDim.x + threadIdx.x) >> 5;
    int lane = threadIdx.x & 31;
    if (warp >= NN) return;
    float4 sc = *(const float4*)(g_scale + lane * 4);
    float4 sh = *(const float4*)(g_shift + lane * 4);
    int g = __ldg(batch + warp);
    float4 v = __ldg((const float4*)(R + warp * HID) + lane);
    v.x = fmaf(v.x, sc.x, sh.x);
    v.y = fmaf(v.y, sc.y, sh.y);
    v.z = fmaf(v.z, sc.z, sh.z);
    v.w = fmaf(v.w, sc.w, sh.w);
    float* p = out + g * HID + lane * 4;
    asm volatile("red.global.add.v4.f32 [%0], {%1,%2,%3,%4};"
                 :: "l"(p), "f"(v.x), "f"(v.y), "f"(v.z), "f"(v.w) : "memory");
}

// ---------------- host ----------------
extern "C" void kernel_launch(void* const* d_in, const int* in_sizes, int n_in,
                              void* d_out, int out_size) {
    const int*   x_idx      = (const int*)d_in[0];
    const int*   edge_index = (const int*)d_in[1];
    const int*   edge_attr  = (const int*)d_in[2];
    const int*   batch      = (const int*)d_in[3];
    const float* node_emb   = (const float*)d_in[4];
    const float* edge_emb   = (const float*)d_in[5];
    const float* W1         = (const float*)d_in[6];
    const float* b1         = (const float*)d_in[7];
    const float* W2         = (const float*)d_in[8];
    const float* b2         = (const float*)d_in[9];
    const float* bn_g       = (const float*)d_in[10];
    const float* bn_b       = (const float*)d_in[11];
    float* out = (float*)d_out;

    cudaFuncSetAttribute(gemm_mma_kernel<false>,
                         cudaFuncAttributeMaxDynamicSharedMemorySize, SMEM_GEMM);
    cudaFuncSetAttribute(gemm_mma_kernel<true>,
                         cudaFuncAttributeMaxDynamicSharedMemorySize, SMEM_GEMM);

    float *Xn, *M, *Ap, *R;
    uint4* Wf;
    cudaGetSymbolAddress((void**)&Xn, g_Xn);
    cudaGetSymbolAddress((void**)&M, g_M);
    cudaGetSymbolAddress((void**)&Ap, g_A);
    cudaGetSymbolAddress((void**)&R, g_R);
    cudaGetSymbolAddress((void**)&Wf, g_Wf);

    int nf4 = NN * (HID / 4);
    int cpBlocks = (nf4 + 255) / 256;
    int gemmBlocks = (NN + MTILE - 1) / MTILE;

    prep_w_kernel<<<(4 * HID * HID + 255) / 256, 256>>>(W1, W2);
    zero_cnt_kernel<<<(NN + 255) / 256, 256>>>();
    hist_kernel<<<(NE + 255) / 256, 256>>>(edge_index);
    scan1_kernel<<<SCAN_BLOCKS, SCAN_B>>>();
    scan2_kernel<<<1, 128>>>();
    scan3_kernel<<<SCAN_BLOCKS, SCAN_B>>>();
    scatter_kernel<<<(NE + 255) / 256, 256>>>(edge_index, edge_attr);
    embed_kernel<<<cpBlocks, 256>>>(x_idx, node_emb);

    for (int l = 0; l < NL; l++) {
        if (l > 0) init_kernel<<<cpBlocks, 256>>>(R);
        aggregate_kernel<<<(NN * 32 + 255) / 256, 256>>>(Xn, M, edge_emb);
        gemm_mma_kernel<false><<<gemmBlocks, 256, SMEM_GEMM>>>(
            M, Wf + (size_t)(l * 2 + 0) * 8192, b1 + l * HID, Ap);
        gemm_mma_kernel<true><<<gemmBlocks, 256, SMEM_GEMM>>>(
            Ap, Wf + (size_t)(l * 2 + 1) * 8192, b2 + l * HID, R);
        finalize_kernel<<<1, 128>>>(bn_g + l * HID, bn_b + l * HID);
    }

    zero_out_kernel<<<(NG * HID + 255) / 256, 256>>>(out);
    pool_kernel<<<NN * 32 / 256, 256>>>(R, batch, out);
}

// round 11
// speedup vs baseline: 1.8683x; 1.1078x over previous
#include <cuda_runtime.h>
#include <cstdint>

#define HID 128
#define NN 50000
#define NE 800000
#define NG 64
#define NL 2

#define SCAN_B 512
#define SCAN_BLOCKS ((NN + SCAN_B - 1) / SCAN_B)   // 98

// ---------------- scratch (static device allocations) ----------------
__device__ __align__(16) float g_Xn[NN * HID];   // normed layer input
__device__ __align__(16) float g_M[NN * HID];    // Xn + aggregation (gemm input)
__device__ __align__(16) float g_R[NN * HID];    // layer raw output
__device__ __align__(16) uint32_t g_Wf[4 * 32768]; // fragment-major hi/lo weights
__device__ int g_cnt[NN];
__device__ int g_off[NN + 1];
__device__ int g_cur[NN];
__device__ int g_bsum[SCAN_BLOCKS];
__device__ int g_boff[SCAN_BLOCKS];
__device__ int g_list[NE];
__device__ double g_sum[HID];
__device__ double g_sumsq[HID];
__device__ __align__(16) float g_scale[HID];
__device__ __align__(16) float g_shift[HID];

__device__ __forceinline__ uint32_t f2tf32(float v) {
    uint32_t o;
    asm("cvt.rna.tf32.f32 %0, %1;" : "=r"(o) : "f"(v));
    return o;
}
__device__ __forceinline__ void split_tf32(float v, uint32_t& h, uint32_t& l) {
    h = f2tf32(v);
    l = f2tf32(v - __uint_as_float(h));
}

#define MMA_TF32(d, a, b) \
    asm volatile("mma.sync.aligned.m16n8k8.row.col.f32.tf32.tf32.f32 " \
        "{%0,%1,%2,%3}, {%4,%5,%6,%7}, {%8,%9}, {%0,%1,%2,%3};" \
        : "+f"((d)[0]), "+f"((d)[1]), "+f"((d)[2]), "+f"((d)[3]) \
        : "r"((a)[0]), "r"((a)[1]), "r"((a)[2]), "r"((a)[3]), \
          "r"((b)[0]), "r"((b)[1]))

// ---------------- weight prep: fragment-major hi/lo layout ----------------
__global__ void prep_w_kernel(const float* __restrict__ W1, const float* __restrict__ W2) {
    int i = blockIdx.x * blockDim.x + threadIdx.x;
    if (i >= 4 * HID * HID) return;
    int w = i >> 14;
    int k = (i >> 7) & 127;
    int n = i & 127;
    int l = w >> 1;
    const float* W = (w & 1) ? W2 : W1;
    float v = __ldg(W + l * HID * HID + k * HID + n);
    uint32_t h, lo;
    split_tf32(v, h, lo);
    int lane = (n & 7) * 4 + (k & 3);
    int word = (k >> 2) & 1;
    int base4 = ((w * 256 + (k >> 3) * 16 + (n >> 3)) * 32 + lane) * 4;
    g_Wf[base4 + word] = h;
    g_Wf[base4 + 2 + word] = lo;
}

// ---------------- CSR build (once per call; graph is layer-invariant) ----------------
__global__ void zero_cnt_kernel() {
    int i = blockIdx.x * blockDim.x + threadIdx.x;
    if (i < NN) g_cnt[i] = 0;
}
__global__ void hist_kernel(const int* __restrict__ ei) {
    int e = blockIdx.x * blockDim.x + threadIdx.x;
    if (e < NE) atomicAdd(&g_cnt[__ldg(ei + NE + e)], 1);
}
__global__ void scan1_kernel() {
    __shared__ int sh[SCAN_B];
    int tid = threadIdx.x;
    int i = blockIdx.x * SCAN_B + tid;
    int v = (i < NN) ? g_cnt[i] : 0;
    sh[tid] = v;
    __syncthreads();
#pragma unroll
    for (int d = 1; d < SCAN_B; d <<= 1) {
        int t = (tid >= d) ? sh[tid - d] : 0;
        __syncthreads();
        sh[tid] += t;
        __syncthreads();
    }
    if (i < NN) g_off[i] = sh[tid] - v;
    if (tid == SCAN_B - 1) g_bsum[blockIdx.x] = sh[tid];
}
__global__ void scan2_kernel() {
    __shared__ int sh[128];
    int tid = threadIdx.x;
    int v = (tid < SCAN_BLOCKS) ? g_bsum[tid] : 0;
    sh[tid] = v;
    __syncthreads();
#pragma unroll
    for (int d = 1; d < 128; d <<= 1) {
        int t = (tid >= d) ? sh[tid - d] : 0;
        __syncthreads();
        sh[tid] += t;
        __syncthreads();
    }
    if (tid < SCAN_BLOCKS) g_boff[tid] = sh[tid] - v;
}
__global__ void scan3_kernel() {
    int i = blockIdx.x * SCAN_B + threadIdx.x;
    if (i < NN) {
        int o = g_off[i] + g_boff[blockIdx.x];
        g_off[i] = o;
        g_cur[i] = o;
    }
    if (i == 0) g_off[NN] = NE;
}
__global__ void scatter_kernel(const int* __restrict__ ei, const int* __restrict__ ea) {
    int e = blockIdx.x * blockDim.x + threadIdx.x;
    if (e >= NE) return;
    int src = __ldg(ei + e);
    int dst = __ldg(ei + NE + e);
    int attr = __ldg(ea + e);
    int p = atomicAdd(&g_cur[dst], 1);
    g_list[p] = (src << 2) | attr;
}

// ---------------- embed: Xn = node_emb[x_idx] ----------------
__global__ void embed_kernel(const int* __restrict__ xi, const float* __restrict__ nemb) {
    int i = blockIdx.x * blockDim.x + threadIdx.x;
    if (i >= NN * (HID / 4)) return;
    int n = i >> 5;
    int c = i & 31;
    ((float4*)g_Xn)[i] = __ldg((const float4*)(nemb + xi[n] * HID) + c);
}

// ---------------- init (between layers): Xn = norm(R) ----------------
__global__ void init_kernel(const float* __restrict__ R) {
    int i = blockIdx.x * blockDim.x + threadIdx.x;
    if (i >= NN * (HID / 4)) return;
    int c = i & 31;
    float4 v = __ldg((const float4*)R + i);
    float4 sc = *(const float4*)(g_scale + c * 4);
    float4 sh = *(const float4*)(g_shift + c * 4);
    v.x = fmaf(v.x, sc.x, sh.x);
    v.y = fmaf(v.y, sc.y, sh.y);
    v.z = fmaf(v.z, sc.z, sh.z);
    v.w = fmaf(v.w, sc.w, sh.w);
    ((float4*)g_Xn)[i] = v;
}

// ---------------- aggregate: M[n] = Xn[n] + sum_{e->n} relu(Xn[src]+eemb[attr]) ----------------
__global__ void aggregate_kernel(const float* __restrict__ Xn, float* __restrict__ M,
                                 const float* __restrict__ eemb) {
    int node = (blockIdx.x * blockDim.x + threadIdx.x) >> 5;
    int lane = threadIdx.x & 31;
    if (node >= NN) return;
    int s = g_off[node];
    int e = g_off[node + 1];
    float4 acc = __ldg((const float4*)(Xn + node * HID) + lane);
    for (int i = s; i < e; i++) {
        int pk = __ldg(g_list + i);
        int src = pk >> 2, attr = pk & 3;
        float4 x4 = __ldg((const float4*)(Xn + src * HID) + lane);
        float4 e4 = __ldg((const float4*)(eemb + attr * HID) + lane);
        acc.x += fmaxf(x4.x + e4.x, 0.f);
        acc.y += fmaxf(x4.y + e4.y, 0.f);
        acc.z += fmaxf(x4.z + e4.z, 0.f);
        acc.w += fmaxf(x4.w + e4.w, 0.f);
    }
    *((float4*)(M + node * HID) + lane) = acc;
}

// ---------------- fused 3xTF32 double-GEMM: R = relu(relu(M@W1+b1)@W2+b2) ----------------
// Phase 1: A from global M (cp.async double-buffered), acc1 -> relu+bias -> smem As.
// Phase 2: A fragments from smem As (stride 132 -> conflict-free), W2 frags from global.
// BN column stats accumulated on the final output.
// Block 256 thr, CTA tile 128x128, warp grid 4Mx2N, warp tile 32x64, 2 CTA/SM.
#define MTILE 128
#define RS 36
#define RS2 132
#define RAW_WORDS (MTILE * RS)
#define STAT_OFF (2 * RAW_WORDS)
#define AS_OFF (STAT_OFF + 256)
#define SMEM_GEMM ((AS_OFF + MTILE * RS2) * 4)

__global__ void __launch_bounds__(256, 2)
fused_gemm_kernel(const float* __restrict__ M, const uint4* __restrict__ Wf1,
                  const float* __restrict__ b1, const uint4* __restrict__ Wf2,
                  const float* __restrict__ b2, float* __restrict__ R) {
    extern __shared__ char smem[];
    float* raw = (float*)smem;
    float* ssum = (float*)smem + STAT_OFF;
    float* ssq = ssum + 128;
    float* As = (float*)smem + AS_OFF;

    uint32_t rawAddr;
    asm("{ .reg .u64 t; cvta.to.shared.u64 t, %1; cvt.u32.u64 %0, t; }"
        : "=r"(rawAddr) : "l"(smem));

    int tid = threadIdx.x, wid = tid >> 5, lane = tid & 31;
    int wm = wid & 3, wn = wid >> 2;
    int g = lane >> 2, tg = lane & 3;
    int rowBase = blockIdx.x * MTILE;

    ssum[tid] = 0.f;   // 256 threads cover ssum+ssq

    auto issue_chunk = [&](int chunk, int buf) {
#pragma unroll
        for (int j = 0; j < 4; j++) {
            int i = tid + j * 256;
            int r = i >> 3, q = i & 7;
            int grow = rowBase + r;
            const float* src = M + (size_t)min(grow, NN - 1) * HID + chunk * 32 + q * 4;
            uint32_t dst = rawAddr + (uint32_t)(buf * RAW_WORDS + r * RS + q * 4) * 4u;
            int sz = (grow < NN) ? 16 : 0;
            asm volatile("cp.async.cg.shared.global [%0], [%1], 16, %2;"
                         :: "r"(dst), "l"(src), "r"(sz));
        }
        asm volatile("cp.async.commit_group;");
    };
    issue_chunk(0, 0);
    issue_chunk(1, 1);

    float acc[2][8][4];
#pragma unroll
    for (int mt = 0; mt < 2; mt++)
#pragma unroll
        for (int nt = 0; nt < 8; nt++)
#pragma unroll
            for (int c = 0; c < 4; c++) acc[mt][nt][c] = 0.f;

    // ---------------- phase 1 mainloop: acc1 = M @ W1 ----------------
    const uint4* wfw1 = Wf1 + (size_t)(wn * 8) * 32 + lane;
#pragma unroll
    for (int chunk = 0; chunk < 4; chunk++) {
        if (chunk < 3) asm volatile("cp.async.wait_group 1;" ::: "memory");
        else           asm volatile("cp.async.wait_group 0;" ::: "memory");
        __syncthreads();
        const float* rb = raw + (chunk & 1) * RAW_WORDS;

#pragma unroll
        for (int ks = 0; ks < 4; ks++) {
            int k0 = ks * 8;
            int kstep = chunk * 4 + ks;
            const uint4* wfk = wfw1 + (size_t)kstep * 16 * 32;

            uint32_t afH[2][4], afL[2][4];
#pragma unroll
            for (int mt = 0; mt < 2; mt++) {
                int r = wm * 32 + mt * 16 + g;
                float v0 = rb[r * RS + k0 + tg];
                float v1 = rb[(r + 8) * RS + k0 + tg];
                float v2 = rb[r * RS + k0 + tg + 4];
                float v3 = rb[(r + 8) * RS + k0 + tg + 4];
                split_tf32(v0, afH[mt][0], afL[mt][0]);
                split_tf32(v1, afH[mt][1], afL[mt][1]);
                split_tf32(v2, afH[mt][2], afL[mt][2]);
                split_tf32(v3, afH[mt][3], afL[mt][3]);
            }
#pragma unroll
            for (int hb = 0; hb < 2; hb++) {
                uint4 bf[4];
#pragma unroll
                for (int q = 0; q < 4; q++)
                    bf[q] = __ldg(wfk + (hb * 4 + q) * 32);
#pragma unroll
                for (int mt = 0; mt < 2; mt++)
#pragma unroll
                    for (int q = 0; q < 4; q++) {
                        int nt = hb * 4 + q;
                        uint32_t bh[2] = {bf[q].x, bf[q].y};
                        uint32_t bl[2] = {bf[q].z, bf[q].w};
                        MMA_TF32(acc[mt][nt], afH[mt], bl);
                        MMA_TF32(acc[mt][nt], afL[mt], bh);
                        MMA_TF32(acc[mt][nt], afH[mt], bh);
                    }
            }
        }
        __syncthreads();
        if (chunk < 2) issue_chunk(chunk + 2, chunk & 1);
    }

    // ---------------- phase 1 epilogue: As = relu(acc1 + b1) ----------------
#pragma unroll
    for (int nt = 0; nt < 8; nt++) {
        int col = wn * 64 + nt * 8 + tg * 2;
        float2 bv = __ldg((const float2*)(b1 + col));
#pragma unroll
        for (int mt = 0; mt < 2; mt++) {
            int r = wm * 32 + mt * 16 + g;
            float2 oa, ob;
            oa.x = fmaxf(acc[mt][nt][0] + bv.x, 0.f);
            oa.y = fmaxf(acc[mt][nt][1] + bv.y, 0.f);
            ob.x = fmaxf(acc[mt][nt][2] + bv.x, 0.f);
            ob.y = fmaxf(acc[mt][nt][3] + bv.y, 0.f);
            *(float2*)(As + r * RS2 + col) = oa;
            *(float2*)(As + (r + 8) * RS2 + col) = ob;
            acc[mt][nt][0] = 0.f; acc[mt][nt][1] = 0.f;
            acc[mt][nt][2] = 0.f; acc[mt][nt][3] = 0.f;
        }
    }
    __syncthreads();

    // ---------------- phase 2 mainloop: acc2 = As @ W2 ----------------
    const uint4* wfw2 = Wf2 + (size_t)(wn * 8) * 32 + lane;
#pragma unroll
    for (int kstep = 0; kstep < 16; kstep++) {
        int k0 = kstep * 8;
        const uint4* wfk = wfw2 + (size_t)kstep * 16 * 32;

        uint32_t afH[2][4], afL[2][4];
#pragma unroll
        for (int mt = 0; mt < 2; mt++) {
            int r = wm * 32 + mt * 16 + g;
            float v0 = As[r * RS2 + k0 + tg];
            float v1 = As[(r + 8) * RS2 + k0 + tg];
            float v2 = As[r * RS2 + k0 + tg + 4];
            float v3 = As[(r + 8) * RS2 + k0 + tg + 4];
            split_tf32(v0, afH[mt][0], afL[mt][0]);
            split_tf32(v1, afH[mt][1], afL[mt][1]);
            split_tf32(v2, afH[mt][2], afL[mt][2]);
            split_tf32(v3, afH[mt][3], afL[mt][3]);
        }
#pragma unroll
        for (int hb = 0; hb < 2; hb++) {
            uint4 bf[4];
#pragma unroll
            for (int q = 0; q < 4; q++)
                bf[q] = __ldg(wfk + (hb * 4 + q) * 32);
#pragma unroll
            for (int mt = 0; mt < 2; mt++)
#pragma unroll
                for (int q = 0; q < 4; q++) {
                    int nt = hb * 4 + q;
                    uint32_t bh[2] = {bf[q].x, bf[q].y};
                    uint32_t bl[2] = {bf[q].z, bf[q].w};
                    MMA_TF32(acc[mt][nt], afH[mt], bl);
                    MMA_TF32(acc[mt][nt], afL[mt], bh);
                    MMA_TF32(acc[mt][nt], afH[mt], bh);
                }
        }
    }

    // ---------------- phase 2 epilogue: R = relu(acc2 + b2), column stats ----------------
#pragma unroll
    for (int nt = 0; nt < 8; nt++) {
        int col = wn * 64 + nt * 8 + tg * 2;
        float2 bv = __ldg((const float2*)(b2 + col));
        float s0 = 0.f, s1 = 0.f, q0 = 0.f, q1 = 0.f;
#pragma unroll
        for (int mt = 0; mt < 2; mt++) {
            int r0 = rowBase + wm * 32 + mt * 16 + g;
            float2 oa, ob;
            oa.x = fmaxf(acc[mt][nt][0] + bv.x, 0.f);
            oa.y = fmaxf(acc[mt][nt][1] + bv.y, 0.f);
            ob.x = fmaxf(acc[mt][nt][2] + bv.x, 0.f);
            ob.y = fmaxf(acc[mt][nt][3] + bv.y, 0.f);
            if (r0 < NN) {
                *(float2*)(R + r0 * HID + col) = oa;
                s0 += oa.x; q0 += oa.x * oa.x; s1 += oa.y; q1 += oa.y * oa.y;
            }
            if (r0 + 8 < NN) {
                *(float2*)(R + (r0 + 8) * HID + col) = ob;
                s0 += ob.x; q0 += ob.x * ob.x; s1 += ob.y; q1 += ob.y * ob.y;
            }
        }
#pragma unroll
        for (int m = 16; m >= 4; m >>= 1) {
            s0 += __shfl_xor_sync(0xffffffff, s0, m);
            s1 += __shfl_xor_sync(0xffffffff, s1, m);
            q0 += __shfl_xor_sync(0xffffffff, q0, m);
            q1 += __shfl_xor_sync(0xffffffff, q1, m);
        }
        if (lane < 4) {
            int c0 = wn * 64 + nt * 8 + lane * 2;
            atomicAdd(&ssum[c0], s0);
            atomicAdd(&ssum[c0 + 1], s1);
            atomicAdd(&ssq[c0], q0);
            atomicAdd(&ssq[c0 + 1], q1);
        }
    }
    __syncthreads();
    if (tid < 128) {
        atomicAdd(&g_sum[tid], (double)ssum[tid]);
        atomicAdd(&g_sumsq[tid], (double)ssq[tid]);
    }
}

// ---------------- finalize: scale/shift from stats; reset accumulators ----------------
__global__ void finalize_kernel(const float* __restrict__ gw, const float* __restrict__ bw) {
    int c = threadIdx.x;
    double mu = g_sum[c] / (double)NN;
    double var = g_sumsq[c] / (double)NN - mu * mu;
    float sc = (float)((double)gw[c] * rsqrt(var + 1e-5));
    g_scale[c] = sc;
    g_shift[c] = bw[c] - (float)mu * sc;
    g_sum[c] = 0.0;
    g_sumsq[c] = 0.0;
}

// ---------------- pooling (applies final norm inline) ----------------
__global__ void zero_out_kernel(float* out) {
    int i = blockIdx.x * blockDim.x + threadIdx.x;
    if (i < NG * HID) out[i] = 0.f;
}

__global__ void pool_kernel(const float* __restrict__ R, const int* __restrict__ batch,
                            float* __restrict__ out) {
    int warp = (blockIdx.x * blockDim.x + threadIdx.x) >> 5;
    int lane = threadIdx.x & 31;
    if (warp >= NN) return;
    float4 sc = *(const float4*)(g_scale + lane * 4);
    float4 sh = *(const float4*)(g_shift + lane * 4);
    int g = __ldg(batch + warp);
    float4 v = __ldg((const float4*)(R + warp * HID) + lane);
    v.x = fmaf(v.x, sc.x, sh.x);
    v.y = fmaf(v.y, sc.y, sh.y);
    v.z = fmaf(v.z, sc.z, sh.z);
    v.w = fmaf(v.w, sc.w, sh.w);
    float* p = out + g * HID + lane * 4;
    asm volatile("red.global.add.v4.f32 [%0], {%1,%2,%3,%4};"
                 :: "l"(p), "f"(v.x), "f"(v.y), "f"(v.z), "f"(v.w) : "memory");
}

// ---------------- host ----------------
extern "C" void kernel_launch(void* const* d_in, const int* in_sizes, int n_in,
                              void* d_out, int out_size) {
    const int*   x_idx      = (const int*)d_in[0];
    const int*   edge_index = (const int*)d_in[1];
    const int*   edge_attr  = (const int*)d_in[2];
    const int*   batch      = (const int*)d_in[3];
    const float* node_emb   = (const float*)d_in[4];
    const float* edge_emb   = (const float*)d_in[5];
    const float* W1         = (const float*)d_in[6];
    const float* b1         = (const float*)d_in[7];
    const float* W2         = (const float*)d_in[8];
    const float* b2         = (const float*)d_in[9];
    const float* bn_g       = (const float*)d_in[10];
    const float* bn_b       = (const float*)d_in[11];
    float* out = (float*)d_out;

    cudaFuncSetAttribute(fused_gemm_kernel,
                         cudaFuncAttributeMaxDynamicSharedMemorySize, SMEM_GEMM);

    float *Xn, *M, *R;
    uint4* Wf;
    cudaGetSymbolAddress((void**)&Xn, g_Xn);
    cudaGetSymbolAddress((void**)&M, g_M);
    cudaGetSymbolAddress((void**)&R, g_R);
    cudaGetSymbolAddress((void**)&Wf, g_Wf);

    int nf4 = NN * (HID / 4);
    int cpBlocks = (nf4 + 255) / 256;
    int gemmBlocks = (NN + MTILE - 1) / MTILE;

    prep_w_kernel<<<(4 * HID * HID + 255) / 256, 256>>>(W1, W2);
    zero_cnt_kernel<<<(NN + 255) / 256, 256>>>();
    hist_kernel<<<(NE + 255) / 256, 256>>>(edge_index);
    scan1_kernel<<<SCAN_BLOCKS, SCAN_B>>>();
    scan2_kernel<<<1, 128>>>();
    scan3_kernel<<<SCAN_BLOCKS, SCAN_B>>>();
    scatter_kernel<<<(NE + 255) / 256, 256>>>(edge_index, edge_attr);
    embed_kernel<<<cpBlocks, 256>>>(x_idx, node_emb);

    for (int l = 0; l < NL; l++) {
        if (l > 0) init_kernel<<<cpBlocks, 256>>>(R);
        aggregate_kernel<<<(NN * 32 + 255) / 256, 256>>>(Xn, M, edge_emb);
        fused_gemm_kernel<<<gemmBlocks, 256, SMEM_GEMM>>>(
            M, Wf + (size_t)(l * 2 + 0) * 8192, b1 + l * HID,
            Wf + (size_t)(l * 2 + 1) * 8192, b2 + l * HID, R);
        finalize_kernel<<<1, 128>>>(bn_g + l * HID, bn_b + l * HID);
    }

    zero_out_kernel<<<(NG * HID + 255) / 256, 256>>>(out);
    pool_kernel<<<NN * 32 / 256, 256>>>(R, batch, out);
}